// round 8
// baseline (speedup 1.0000x reference)
#include <cuda_runtime.h>
#include <cuda_fp16.h>

#define BB 128  // batch
#define BU 32   // batch in uint2 units (4 halves each)

// ---------------- padded geometry, fp16 (halos stay zero: never written) ---
__device__ __align__(16) __half g_bin[9 * 34 * 34 * BB];
__device__ __align__(16) __half g_h1[32 * 18 * 18 * BB];
__device__ __align__(16) __half g_h2[128 * 10 * 10 * BB];
__device__ __align__(16) __half g_h3[512 * 6 * 6 * BB];
__device__ __align__(16) __half g_h4[4096 * BB];
__device__ __align__(16) __half g_g1[40960 * BB];
__device__ __align__(16) __half g_g2[20480 * BB];
__device__ __align__(16) __half2 g_mixh[83552 * 4];
__device__ __align__(16) float g_part[160 * BB];

__constant__ float GC[64] = {
    0, 0, 0, 0,   0, 0, 0, 1,   0, 1, 0, -1,  0, 1, 0, 0,
    0, 0, 1, -1,  0, 0, 1, 0,   0, 1, 1, -2,  0, 1, 1, -1,
    1, -1, -1, 1, 1, -1, -1, 2, 1, 0, -1, 0,  1, 0, -1, 1,
    1, -1, 0, 0,  1, -1, 0, 1,  1, 0, 0, -1,  1, 0, 0, 0};

#define OFF_C1 0
#define OFF_C2 224
#define OFF_C3 1120
#define OFF_C4 4704
#define OFF_L1 11872
#define OFF_L2 52832
#define OFF_L3 73312
#define N_NODES 83552

// ---------------- helpers ----------------
__device__ __forceinline__ __half2 u2h(unsigned int u) {
    __half2 h;
    *reinterpret_cast<unsigned int*>(&h) = u;
    return h;
}
__device__ __forceinline__ unsigned int h2u(__half2 h) {
    return *reinterpret_cast<unsigned int*>(&h);
}
__device__ __forceinline__ __half2 gateh(__half2 a, __half2 b,
                                         __half2 w0, __half2 w1, __half2 w2, __half2 w3) {
    return __hfma2(__hmul2(a, b), w3, __hfma2(b, w2, __hfma2(a, w1, w0)));
}

// ---------------- kernel 1: gate mixing -> duplicated half2 coefs ----------
__global__ void mix_kernel(const float* __restrict__ s0, const float* __restrict__ s1,
                           const float* __restrict__ s2, const float* __restrict__ s3,
                           const float* __restrict__ s4, const float* __restrict__ s5,
                           const float* __restrict__ s6, __half2* __restrict__ dst) {
    int tid = blockIdx.x * blockDim.x + threadIdx.x;
    if (tid >= N_NODES) return;
    const int offs[8] = {OFF_C1, OFF_C2, OFF_C3, OFF_C4, OFF_L1, OFF_L2, OFF_L3, N_NODES};
    const float* srcs[7] = {s0, s1, s2, s3, s4, s5, s6};
    int seg = 0;
    while (tid >= offs[seg + 1]) seg++;
    const float* w = srcs[seg] + (size_t)(tid - offs[seg]) * 16;

    float e[16];
    float mx = w[0];
#pragma unroll
    for (int i = 1; i < 16; i++) mx = fmaxf(mx, w[i]);
    float s = 0.f;
#pragma unroll
    for (int i = 0; i < 16; i++) { e[i] = __expf(w[i] - mx); s += e[i]; }
    float inv = 1.f / s;
    float m0 = 0.f, m1 = 0.f, m2 = 0.f, m3 = 0.f;
#pragma unroll
    for (int i = 0; i < 16; i++) {
        float p = e[i] * inv;
        m0 = fmaf(p, GC[i * 4 + 0], m0);
        m1 = fmaf(p, GC[i * 4 + 1], m1);
        m2 = fmaf(p, GC[i * 4 + 2], m2);
        m3 = fmaf(p, GC[i * 4 + 3], m3);
    }
    dst[tid * 4 + 0] = __float2half2_rn(m0);
    dst[tid * 4 + 1] = __float2half2_rn(m1);
    dst[tid * 4 + 2] = __float2half2_rn(m2);
    dst[tid * 4 + 3] = __float2half2_rn(m3);
}

// ---------------- kernel 2: binarize + BCHW -> CHWB fp16 (padded out) ------
__global__ void binarize_kernel(const float* __restrict__ x, __half* __restrict__ bin) {
    __shared__ float tile[32][33];
    int c = blockIdx.z;
    int h = blockIdx.y;
    int bc = blockIdx.x;
    int b = bc * 32 + threadIdx.y;
    tile[threadIdx.y][threadIdx.x] = x[(((size_t)b * 3 + c) * 32 + h) * 32 + threadIdx.x];
    __syncthreads();
    int w = threadIdx.y;
    int bout = bc * 32 + threadIdx.x;
    float v = tile[threadIdx.x][w];
    const float thr[3] = {0.25f, 0.5f, 0.75f};
    const __half one = __float2half(1.f), zero = __float2half(0.f);
#pragma unroll
    for (int t = 0; t < 3; t++) {
        size_t idx = (((size_t)(t * 3 + c)) * 34 * 34 + (size_t)(h + 1) * 34 + (w + 1)) * BB + bout;
        bin[idx] = (v > thr[t]) ? one : zero;
    }
}

// ---------------- tree_conv + or_pool: pixel-split across ty ---------------
// block (32, 4, SPB): lane=batch uint2, ty=pre-pool pixel, tz=spatial unit
template <int Hin, int SPB, bool PADOUT>
__global__ void __launch_bounds__(128 * SPB) tree_conv_kernel(
    const uint2* __restrict__ in, uint2* __restrict__ out,
    const int* __restrict__ leaf, const __half2* __restrict__ mixh) {
    constexpr int Win = Hin + 2;
    constexpr int Wo = Hin / 2;
    constexpr int Wop = PADOUT ? (Wo + 2) : Wo;
    int o = blockIdx.y;
    __shared__ __half2 smw[28];
    __shared__ int soff[8];
    __shared__ uint2 sres[SPB][4][32];
    int t = (threadIdx.z * 4 + threadIdx.y) * 32 + threadIdx.x;
    if (t < 28) smw[t] = mixh[o * 28 + t];
    if (t < 8) {
        int idx = leaf[o * 8 + t];
        int ch = idx / 9, p = idx % 9;
        soff[t] = (ch * Win * Win + (p / 3) * Win + (p % 3)) * BU;
    }
    __syncthreads();

    int s = blockIdx.x * SPB + threadIdx.z;
    int wo = s % Wo, ho = s / Wo;
    int q = threadIdx.y;          // which pre-pool pixel
    int lane = threadIdx.x;
    int pos = ((2 * ho + (q >> 1)) * Win + (2 * wo + (q & 1))) * BU + lane;

    uint2 v[8];
#pragma unroll
    for (int l = 0; l < 8; l++) v[l] = in[soff[l] + pos];

    // low half2
    __half2 t0 = gateh(u2h(v[0].x), u2h(v[1].x), smw[0], smw[1], smw[2], smw[3]);
    __half2 t1 = gateh(u2h(v[2].x), u2h(v[3].x), smw[4], smw[5], smw[6], smw[7]);
    __half2 t2 = gateh(u2h(v[4].x), u2h(v[5].x), smw[8], smw[9], smw[10], smw[11]);
    __half2 t3 = gateh(u2h(v[6].x), u2h(v[7].x), smw[12], smw[13], smw[14], smw[15]);
    __half2 u0 = gateh(t0, t1, smw[16], smw[17], smw[18], smw[19]);
    __half2 u1 = gateh(t2, t3, smw[20], smw[21], smw[22], smw[23]);
    __half2 zlo = gateh(u0, u1, smw[24], smw[25], smw[26], smw[27]);
    // high half2
    t0 = gateh(u2h(v[0].y), u2h(v[1].y), smw[0], smw[1], smw[2], smw[3]);
    t1 = gateh(u2h(v[2].y), u2h(v[3].y), smw[4], smw[5], smw[6], smw[7]);
    t2 = gateh(u2h(v[4].y), u2h(v[5].y), smw[8], smw[9], smw[10], smw[11]);
    t3 = gateh(u2h(v[6].y), u2h(v[7].y), smw[12], smw[13], smw[14], smw[15]);
    u0 = gateh(t0, t1, smw[16], smw[17], smw[18], smw[19]);
    u1 = gateh(t2, t3, smw[20], smw[21], smw[22], smw[23]);
    __half2 zhi = gateh(u0, u1, smw[24], smw[25], smw[26], smw[27]);

    sres[threadIdx.z][q][lane] = make_uint2(h2u(zlo), h2u(zhi));
    __syncthreads();

    if (q == 0) {
        uint2 r0 = sres[threadIdx.z][0][lane];
        uint2 r1 = sres[threadIdx.z][1][lane];
        uint2 r2 = sres[threadIdx.z][2][lane];
        uint2 r3 = sres[threadIdx.z][3][lane];
        __half2 rlo = __hmax2(__hmax2(u2h(r0.x), u2h(r1.x)), __hmax2(u2h(r2.x), u2h(r3.x)));
        __half2 rhi = __hmax2(__hmax2(u2h(r0.y), u2h(r1.y)), __hmax2(u2h(r2.y), u2h(r3.y)));
        size_t oidx;
        if (PADOUT)
            oidx = ((size_t)o * Wop * Wop + (size_t)(ho + 1) * Wop + (wo + 1)) * BU + lane;
        else
            oidx = ((size_t)o * Wo * Wo + (size_t)ho * Wo + wo) * BU + lane;
        out[oidx] = make_uint2(h2u(rlo), h2u(rhi));
    }
}

// ---------------- logic layers: fp16, uint2 lanes ----------------
__global__ void logic_kernel(const uint2* __restrict__ in, uint2* __restrict__ out,
                             const int* __restrict__ ai, const int* __restrict__ bi,
                             const __half2* __restrict__ mixh, int Dout) {
    int tid = blockIdx.x * blockDim.x + threadIdx.x;
    if (tid >= Dout * BU) return;
    int j = tid >> 5, lane = tid & 31;
    __half2 w0 = mixh[j * 4 + 0], w1 = mixh[j * 4 + 1];
    __half2 w2 = mixh[j * 4 + 2], w3 = mixh[j * 4 + 3];
    uint2 a = in[(size_t)__ldg(&ai[j]) * BU + lane];
    uint2 b = in[(size_t)__ldg(&bi[j]) * BU + lane];
    __half2 rlo = gateh(u2h(a.x), u2h(b.x), w0, w1, w2, w3);
    __half2 rhi = gateh(u2h(a.y), u2h(b.y), w0, w1, w2, w3);
    out[tid] = make_uint2(h2u(rlo), h2u(rhi));
}

// ---------------- logic3 fused with group-sum partials (float accum) -------
__global__ void __launch_bounds__(128) logic3_sum_kernel(
    const uint2* __restrict__ in, float4* __restrict__ part,
    const int* __restrict__ ai, const int* __restrict__ bi,
    const __half2* __restrict__ mixh) {
    __shared__ float4 red[4][32];
    int blk = blockIdx.x;
    int wz = threadIdx.y;
    int lane = threadIdx.x;
    int j0 = blk * 64 + wz * 16;
    float4 acc = make_float4(0.f, 0.f, 0.f, 0.f);
#pragma unroll
    for (int jj = 0; jj < 16; jj++) {
        int j = j0 + jj;
        __half2 w0 = mixh[j * 4 + 0], w1 = mixh[j * 4 + 1];
        __half2 w2 = mixh[j * 4 + 2], w3 = mixh[j * 4 + 3];
        uint2 a = in[(size_t)__ldg(&ai[j]) * BU + lane];
        uint2 b = in[(size_t)__ldg(&bi[j]) * BU + lane];
        float2 glo = __half22float2(gateh(u2h(a.x), u2h(b.x), w0, w1, w2, w3));
        float2 ghi = __half22float2(gateh(u2h(a.y), u2h(b.y), w0, w1, w2, w3));
        acc.x += glo.x; acc.y += glo.y; acc.z += ghi.x; acc.w += ghi.y;
    }
    red[wz][lane] = acc;
    __syncthreads();
    if (wz == 0) {
        float4 s = red[0][lane], s1 = red[1][lane], s2 = red[2][lane], s3 = red[3][lane];
        s.x += s1.x + s2.x + s3.x;
        s.y += s1.y + s2.y + s3.y;
        s.z += s1.z + s2.z + s3.z;
        s.w += s1.w + s2.w + s3.w;
        part[(size_t)blk * BU + lane] = s;
    }
}

// ---------------- final reduce ----------------
__global__ void final_sum_kernel(const float* __restrict__ part, float* __restrict__ out) {
    int tid = blockIdx.x * blockDim.x + threadIdx.x;
    if (tid >= 1280) return;
    int cls = tid >> 7, b = tid & 127;
    float s = 0.f;
#pragma unroll
    for (int k = 0; k < 16; k++) s += part[(size_t)(cls * 16 + k) * BB + b];
    out[b * 10 + cls] = s * 0.01f;
}

// ---------------- host launcher ----------------
extern "C" void kernel_launch(void* const* d_in, const int* in_sizes, int n_in,
                              void* d_out, int out_size) {
    const float* x   = (const float*)d_in[0];
    const int*   c1i = (const int*)d_in[1];  const float* c1w = (const float*)d_in[2];
    const int*   c2i = (const int*)d_in[3];  const float* c2w = (const float*)d_in[4];
    const int*   c3i = (const int*)d_in[5];  const float* c3w = (const float*)d_in[6];
    const int*   c4i = (const int*)d_in[7];  const float* c4w = (const float*)d_in[8];
    const int*   l1a = (const int*)d_in[9];  const int* l1b = (const int*)d_in[10];
    const float* l1w = (const float*)d_in[11];
    const int*   l2a = (const int*)d_in[12]; const int* l2b = (const int*)d_in[13];
    const float* l2w = (const float*)d_in[14];
    const int*   l3a = (const int*)d_in[15]; const int* l3b = (const int*)d_in[16];
    const float* l3w = (const float*)d_in[17];

    __half *bin, *h1, *h2, *h3, *h4, *g1, *g2;
    __half2* mixh;
    float* part;
    cudaGetSymbolAddress((void**)&bin,  g_bin);
    cudaGetSymbolAddress((void**)&h1,   g_h1);
    cudaGetSymbolAddress((void**)&h2,   g_h2);
    cudaGetSymbolAddress((void**)&h3,   g_h3);
    cudaGetSymbolAddress((void**)&h4,   g_h4);
    cudaGetSymbolAddress((void**)&g1,   g_g1);
    cudaGetSymbolAddress((void**)&g2,   g_g2);
    cudaGetSymbolAddress((void**)&mixh, g_mixh);
    cudaGetSymbolAddress((void**)&part, g_part);

    mix_kernel<<<(N_NODES + 127) / 128, 128>>>(c1w, c2w, c3w, c4w, l1w, l2w, l3w, mixh);
    binarize_kernel<<<dim3(4, 32, 3), dim3(32, 32)>>>(x, bin);

    // pixel-split blocks: (32 lanes, 4 pixels, 2 spatial units) = 256 threads
    tree_conv_kernel<32, 2, true> <<<dim3(128, 32),  dim3(32, 4, 2)>>>((const uint2*)bin, (uint2*)h1, c1i, mixh + OFF_C1 * 4);
    tree_conv_kernel<16, 2, true> <<<dim3(32, 128),  dim3(32, 4, 2)>>>((const uint2*)h1,  (uint2*)h2, c2i, mixh + OFF_C2 * 4);
    tree_conv_kernel<8, 2, true>  <<<dim3(8, 512),   dim3(32, 4, 2)>>>((const uint2*)h2,  (uint2*)h3, c3i, mixh + OFF_C3 * 4);
    tree_conv_kernel<4, 2, false><<<dim3(2, 1024),  dim3(32, 4, 2)>>>((const uint2*)h3,  (uint2*)h4, c4i, mixh + OFF_C4 * 4);

    logic_kernel<<<(40960 * BU) / 256, 256>>>((const uint2*)h4, (uint2*)g1, l1a, l1b, mixh + OFF_L1 * 4, 40960);
    logic_kernel<<<(20480 * BU) / 256, 256>>>((const uint2*)g1, (uint2*)g2, l2a, l2b, mixh + OFF_L2 * 4, 20480);
    logic3_sum_kernel<<<160, dim3(32, 4)>>>((const uint2*)g2, (float4*)part, l3a, l3b, mixh + OFF_L3 * 4);
    final_sum_kernel<<<10, 128>>>(part, (float*)d_out);
}

// round 9
// speedup vs baseline: 1.1271x; 1.1271x over previous
#include <cuda_runtime.h>
#include <cuda_fp16.h>

#define BB 128  // batch
#define BU 32   // batch in uint2 units (4 halves each)

// ---------------- padded geometry, fp16 (halos stay zero: never written) ---
__device__ __align__(16) __half g_bin[9 * 34 * 34 * BB];
__device__ __align__(16) __half g_h1[32 * 18 * 18 * BB];
__device__ __align__(16) __half g_h2[128 * 10 * 10 * BB];
__device__ __align__(16) __half g_h3[512 * 6 * 6 * BB];
__device__ __align__(16) __half g_h4[4096 * BB];
__device__ __align__(16) __half g_g1[40960 * BB];
__device__ __align__(16) __half g_g2[20480 * BB];
__device__ __align__(16) __half2 g_mixh[83552 * 4];
__device__ __align__(16) float g_part[160 * BB];

__constant__ float GC[64] = {
    0, 0, 0, 0,   0, 0, 0, 1,   0, 1, 0, -1,  0, 1, 0, 0,
    0, 0, 1, -1,  0, 0, 1, 0,   0, 1, 1, -2,  0, 1, 1, -1,
    1, -1, -1, 1, 1, -1, -1, 2, 1, 0, -1, 0,  1, 0, -1, 1,
    1, -1, 0, 0,  1, -1, 0, 1,  1, 0, 0, -1,  1, 0, 0, 0};

#define OFF_C1 0
#define OFF_C2 224
#define OFF_C3 1120
#define OFF_C4 4704
#define OFF_L1 11872
#define OFF_L2 52832
#define OFF_L3 73312
#define N_NODES 83552

// ---------------- helpers ----------------
__device__ __forceinline__ __half2 u2h(unsigned int u) {
    __half2 h;
    *reinterpret_cast<unsigned int*>(&h) = u;
    return h;
}
__device__ __forceinline__ unsigned int h2u(__half2 h) {
    return *reinterpret_cast<unsigned int*>(&h);
}
// Horner: (w0 + w1*a) + b*(w2 + w3*a) — 3 HFMA2, depth 2
__device__ __forceinline__ __half2 gateh(__half2 a, __half2 b,
                                         __half2 w0, __half2 w1, __half2 w2, __half2 w3) {
    __half2 u = __hfma2(a, w1, w0);
    __half2 t = __hfma2(a, w3, w2);
    return __hfma2(b, t, u);
}

// ---------------- kernel 1: gate mixing -> duplicated half2 coefs ----------
__global__ void mix_kernel(const float* __restrict__ s0, const float* __restrict__ s1,
                           const float* __restrict__ s2, const float* __restrict__ s3,
                           const float* __restrict__ s4, const float* __restrict__ s5,
                           const float* __restrict__ s6, __half2* __restrict__ dst) {
    int tid = blockIdx.x * blockDim.x + threadIdx.x;
    if (tid >= N_NODES) return;
    const int offs[8] = {OFF_C1, OFF_C2, OFF_C3, OFF_C4, OFF_L1, OFF_L2, OFF_L3, N_NODES};
    const float* srcs[7] = {s0, s1, s2, s3, s4, s5, s6};
    int seg = 0;
    while (tid >= offs[seg + 1]) seg++;
    const float* w = srcs[seg] + (size_t)(tid - offs[seg]) * 16;

    float e[16];
    float mx = w[0];
#pragma unroll
    for (int i = 1; i < 16; i++) mx = fmaxf(mx, w[i]);
    float s = 0.f;
#pragma unroll
    for (int i = 0; i < 16; i++) { e[i] = __expf(w[i] - mx); s += e[i]; }
    float inv = 1.f / s;
    float m0 = 0.f, m1 = 0.f, m2 = 0.f, m3 = 0.f;
#pragma unroll
    for (int i = 0; i < 16; i++) {
        float p = e[i] * inv;
        m0 = fmaf(p, GC[i * 4 + 0], m0);
        m1 = fmaf(p, GC[i * 4 + 1], m1);
        m2 = fmaf(p, GC[i * 4 + 2], m2);
        m3 = fmaf(p, GC[i * 4 + 3], m3);
    }
    dst[tid * 4 + 0] = __float2half2_rn(m0);
    dst[tid * 4 + 1] = __float2half2_rn(m1);
    dst[tid * 4 + 2] = __float2half2_rn(m2);
    dst[tid * 4 + 3] = __float2half2_rn(m3);
}

// ---------------- kernel 2: binarize + BCHW -> CHWB fp16 (padded out) ------
__global__ void binarize_kernel(const float* __restrict__ x, __half* __restrict__ bin) {
    __shared__ float tile[32][33];
    int c = blockIdx.z;
    int h = blockIdx.y;
    int bc = blockIdx.x;
    int b = bc * 32 + threadIdx.y;
    tile[threadIdx.y][threadIdx.x] = x[(((size_t)b * 3 + c) * 32 + h) * 32 + threadIdx.x];
    __syncthreads();
    int w = threadIdx.y;
    int bout = bc * 32 + threadIdx.x;
    float v = tile[threadIdx.x][w];
    const float thr[3] = {0.25f, 0.5f, 0.75f};
    const __half one = __float2half(1.f), zero = __float2half(0.f);
#pragma unroll
    for (int t = 0; t < 3; t++) {
        size_t idx = (((size_t)(t * 3 + c)) * 34 * 34 + (size_t)(h + 1) * 34 + (w + 1)) * BB + bout;
        bin[idx] = (v > thr[t]) ? one : zero;
    }
}

// ---------------- tree_conv + or_pool: fp16, 32 uint2-lanes per (o,s) ------
template <int Hin, int SPB, bool PADOUT>
__global__ void __launch_bounds__(32 * SPB, 4) tree_conv_kernel(
    const uint2* __restrict__ in, uint2* __restrict__ out,
    const int* __restrict__ leaf, const __half2* __restrict__ mixh) {
    constexpr int Win = Hin + 2;
    constexpr int Wo = Hin / 2;
    constexpr int Wop = PADOUT ? (Wo + 2) : Wo;
    int o = blockIdx.y;
    __shared__ __half2 smw[28];
    __shared__ int soff[8];
    int t = threadIdx.y * 32 + threadIdx.x;
    if (t < 28) smw[t] = mixh[o * 28 + t];
    if (t < 8) {
        int idx = leaf[o * 8 + t];
        int ch = idx / 9, p = idx % 9;
        soff[t] = (ch * Win * Win + (p / 3) * Win + (p % 3)) * BU;
    }
    __syncthreads();
    int s = blockIdx.x * SPB + threadIdx.y;
    int wo = s % Wo, ho = s / Wo;
    int lane = threadIdx.x;

    __half2 rlo = __float2half2_rn(-60000.f);
    __half2 rhi = rlo;
#pragma unroll
    for (int ph = 0; ph < 2; ph++) {
#pragma unroll
        for (int pw = 0; pw < 2; pw++) {
            int pos = ((2 * ho + ph) * Win + (2 * wo + pw)) * BU + lane;
            uint2 v[8];
#pragma unroll
            for (int l = 0; l < 8; l++) v[l] = in[soff[l] + pos];
            // low half2 (batch 4*lane .. +1)
            __half2 t0 = gateh(u2h(v[0].x), u2h(v[1].x), smw[0], smw[1], smw[2], smw[3]);
            __half2 t1 = gateh(u2h(v[2].x), u2h(v[3].x), smw[4], smw[5], smw[6], smw[7]);
            __half2 t2 = gateh(u2h(v[4].x), u2h(v[5].x), smw[8], smw[9], smw[10], smw[11]);
            __half2 t3 = gateh(u2h(v[6].x), u2h(v[7].x), smw[12], smw[13], smw[14], smw[15]);
            __half2 u0 = gateh(t0, t1, smw[16], smw[17], smw[18], smw[19]);
            __half2 u1 = gateh(t2, t3, smw[20], smw[21], smw[22], smw[23]);
            rlo = __hmax2(rlo, gateh(u0, u1, smw[24], smw[25], smw[26], smw[27]));
            // high half2 (batch 4*lane+2 .. +3)
            t0 = gateh(u2h(v[0].y), u2h(v[1].y), smw[0], smw[1], smw[2], smw[3]);
            t1 = gateh(u2h(v[2].y), u2h(v[3].y), smw[4], smw[5], smw[6], smw[7]);
            t2 = gateh(u2h(v[4].y), u2h(v[5].y), smw[8], smw[9], smw[10], smw[11]);
            t3 = gateh(u2h(v[6].y), u2h(v[7].y), smw[12], smw[13], smw[14], smw[15]);
            u0 = gateh(t0, t1, smw[16], smw[17], smw[18], smw[19]);
            u1 = gateh(t2, t3, smw[20], smw[21], smw[22], smw[23]);
            rhi = __hmax2(rhi, gateh(u0, u1, smw[24], smw[25], smw[26], smw[27]));
        }
    }
    size_t oidx;
    if (PADOUT)
        oidx = ((size_t)o * Wop * Wop + (size_t)(ho + 1) * Wop + (wo + 1)) * BU + lane;
    else
        oidx = ((size_t)o * Wo * Wo + (size_t)ho * Wo + wo) * BU + lane;
    out[oidx] = make_uint2(h2u(rlo), h2u(rhi));
}

// ---------------- logic layers: fp16, uint2 lanes ----------------
__global__ void logic_kernel(const uint2* __restrict__ in, uint2* __restrict__ out,
                             const int* __restrict__ ai, const int* __restrict__ bi,
                             const __half2* __restrict__ mixh, int Dout) {
    int tid = blockIdx.x * blockDim.x + threadIdx.x;
    if (tid >= Dout * BU) return;
    int j = tid >> 5, lane = tid & 31;
    __half2 w0 = mixh[j * 4 + 0], w1 = mixh[j * 4 + 1];
    __half2 w2 = mixh[j * 4 + 2], w3 = mixh[j * 4 + 3];
    uint2 a = in[(size_t)__ldg(&ai[j]) * BU + lane];
    uint2 b = in[(size_t)__ldg(&bi[j]) * BU + lane];
    __half2 rlo = gateh(u2h(a.x), u2h(b.x), w0, w1, w2, w3);
    __half2 rhi = gateh(u2h(a.y), u2h(b.y), w0, w1, w2, w3);
    out[tid] = make_uint2(h2u(rlo), h2u(rhi));
}

// ---------------- logic3 fused with group-sum partials (float accum) -------
__global__ void __launch_bounds__(128) logic3_sum_kernel(
    const uint2* __restrict__ in, float4* __restrict__ part,
    const int* __restrict__ ai, const int* __restrict__ bi,
    const __half2* __restrict__ mixh) {
    __shared__ float4 red[4][32];
    int blk = blockIdx.x;
    int wz = threadIdx.y;
    int lane = threadIdx.x;
    int j0 = blk * 64 + wz * 16;
    float4 acc = make_float4(0.f, 0.f, 0.f, 0.f);
#pragma unroll
    for (int jj = 0; jj < 16; jj++) {
        int j = j0 + jj;
        __half2 w0 = mixh[j * 4 + 0], w1 = mixh[j * 4 + 1];
        __half2 w2 = mixh[j * 4 + 2], w3 = mixh[j * 4 + 3];
        uint2 a = in[(size_t)__ldg(&ai[j]) * BU + lane];
        uint2 b = in[(size_t)__ldg(&bi[j]) * BU + lane];
        float2 glo = __half22float2(gateh(u2h(a.x), u2h(b.x), w0, w1, w2, w3));
        float2 ghi = __half22float2(gateh(u2h(a.y), u2h(b.y), w0, w1, w2, w3));
        acc.x += glo.x; acc.y += glo.y; acc.z += ghi.x; acc.w += ghi.y;
    }
    red[wz][lane] = acc;
    __syncthreads();
    if (wz == 0) {
        float4 s = red[0][lane], s1 = red[1][lane], s2 = red[2][lane], s3 = red[3][lane];
        s.x += s1.x + s2.x + s3.x;
        s.y += s1.y + s2.y + s3.y;
        s.z += s1.z + s2.z + s3.z;
        s.w += s1.w + s2.w + s3.w;
        part[(size_t)blk * BU + lane] = s;
    }
}

// ---------------- final reduce ----------------
__global__ void final_sum_kernel(const float* __restrict__ part, float* __restrict__ out) {
    int tid = blockIdx.x * blockDim.x + threadIdx.x;
    if (tid >= 1280) return;
    int cls = tid >> 7, b = tid & 127;
    float s = 0.f;
#pragma unroll
    for (int k = 0; k < 16; k++) s += part[(size_t)(cls * 16 + k) * BB + b];
    out[b * 10 + cls] = s * 0.01f;
}

// ---------------- host launcher ----------------
extern "C" void kernel_launch(void* const* d_in, const int* in_sizes, int n_in,
                              void* d_out, int out_size) {
    const float* x   = (const float*)d_in[0];
    const int*   c1i = (const int*)d_in[1];  const float* c1w = (const float*)d_in[2];
    const int*   c2i = (const int*)d_in[3];  const float* c2w = (const float*)d_in[4];
    const int*   c3i = (const int*)d_in[5];  const float* c3w = (const float*)d_in[6];
    const int*   c4i = (const int*)d_in[7];  const float* c4w = (const float*)d_in[8];
    const int*   l1a = (const int*)d_in[9];  const int* l1b = (const int*)d_in[10];
    const float* l1w = (const float*)d_in[11];
    const int*   l2a = (const int*)d_in[12]; const int* l2b = (const int*)d_in[13];
    const float* l2w = (const float*)d_in[14];
    const int*   l3a = (const int*)d_in[15]; const int* l3b = (const int*)d_in[16];
    const float* l3w = (const float*)d_in[17];

    __half *bin, *h1, *h2, *h3, *h4, *g1, *g2;
    __half2* mixh;
    float* part;
    cudaGetSymbolAddress((void**)&bin,  g_bin);
    cudaGetSymbolAddress((void**)&h1,   g_h1);
    cudaGetSymbolAddress((void**)&h2,   g_h2);
    cudaGetSymbolAddress((void**)&h3,   g_h3);
    cudaGetSymbolAddress((void**)&h4,   g_h4);
    cudaGetSymbolAddress((void**)&g1,   g_g1);
    cudaGetSymbolAddress((void**)&g2,   g_g2);
    cudaGetSymbolAddress((void**)&mixh, g_mixh);
    cudaGetSymbolAddress((void**)&part, g_part);

    mix_kernel<<<(N_NODES + 127) / 128, 128>>>(c1w, c2w, c3w, c4w, l1w, l2w, l3w, mixh);
    binarize_kernel<<<dim3(4, 32, 3), dim3(32, 32)>>>(x, bin);

    tree_conv_kernel<32, 8, true> <<<dim3(32, 32),  dim3(32, 8)>>>((const uint2*)bin, (uint2*)h1, c1i, mixh + OFF_C1 * 4);
    tree_conv_kernel<16, 8, true> <<<dim3(8, 128),  dim3(32, 8)>>>((const uint2*)h1,  (uint2*)h2, c2i, mixh + OFF_C2 * 4);
    tree_conv_kernel<8, 8, true>  <<<dim3(2, 512),  dim3(32, 8)>>>((const uint2*)h2,  (uint2*)h3, c3i, mixh + OFF_C3 * 4);
    tree_conv_kernel<4, 4, false><<<dim3(1, 1024), dim3(32, 4)>>>((const uint2*)h3,  (uint2*)h4, c4i, mixh + OFF_C4 * 4);

    logic_kernel<<<(40960 * BU) / 256, 256>>>((const uint2*)h4, (uint2*)g1, l1a, l1b, mixh + OFF_L1 * 4, 40960);
    logic_kernel<<<(20480 * BU) / 256, 256>>>((const uint2*)g1, (uint2*)g2, l2a, l2b, mixh + OFF_L2 * 4, 20480);
    logic3_sum_kernel<<<160, dim3(32, 4)>>>((const uint2*)g2, (float4*)part, l3a, l3b, mixh + OFF_L3 * 4);
    final_sum_kernel<<<10, 128>>>(part, (float*)d_out);
}